// round 8
// baseline (speedup 1.0000x reference)
#include <cuda_runtime.h>
#include <cuda_bf16.h>
#include <float.h>
#include <stdint.h>

// Problem constants
#define BB   8
#define NN   2048
#define MM   512
#define CC   256      // channels per source (C1 = C2 = 256)
#define NR   4
#define CIN  512      // C1 + C2
#define CO   256      // output channels of both MLP layers
#define PTOT (BB*NR*NN)   // 65536 positions

// ---------------- scratch (device globals; no runtime allocation) ----------------
__device__ float g_Zt[(size_t)BB*NR*MM*CO];   // Z^T = (W1a @ known_feats)^T (slice, m, o) 16 MB
__device__ float g_y1[(size_t)BB*CO*NR*NN];   // GEMM1 raw output                      64 MB
__device__ float g_y2[(size_t)BB*CO*NR*NN];   // GEMM2 raw output                      64 MB
__device__ int   g_idx[BB*NN*3];
__device__ float g_wgt[BB*NN*3];
__device__ float g_sum1[CO], g_sumsq1[CO], g_s1[CO], g_t1[CO];
__device__ float g_sum2[CO], g_sumsq2[CO], g_s2[CO], g_t2[CO];

// ---------------- tf32 helpers ----------------
__device__ __forceinline__ uint32_t f2tf(float x) {
    uint32_t r;
    asm("cvt.rna.tf32.f32 %0, %1;" : "=r"(r) : "f"(x));
    return r;
}

__device__ __forceinline__ void mma_tf32(float* d, const uint32_t* a, const uint32_t* b) {
    asm volatile(
        "mma.sync.aligned.m16n8k8.row.col.f32.tf32.tf32.f32 "
        "{%0,%1,%2,%3}, {%4,%5,%6,%7}, {%8,%9}, {%0,%1,%2,%3};"
        : "+f"(d[0]), "+f"(d[1]), "+f"(d[2]), "+f"(d[3])
        : "r"(a[0]), "r"(a[1]), "r"(a[2]), "r"(a[3]), "r"(b[0]), "r"(b[1]));
}

// ---------------- GEMM config ----------------
#define TM 128
#define TN 128
#define BK 32
#define SST 136   // smem row stride in words -> conflict-free fragment loads
#define TILE_WORDS (BK*SST)
#define SMEMB (4*TILE_WORDS*4)   // 2 buffers x (A+B) x BK*SST words

// ---------------- shared GEMM building blocks ----------------
__device__ __forceinline__ void store_tile_A(uint32_t* As, const float4* pa,
                                             int o_l, int kA) {
    #pragma unroll
    for (int j = 0; j < 4; j++) {
        const float* e = (const float*)&pa[j];
        #pragma unroll
        for (int t = 0; t < 4; t++)
            As[(kA + j*4 + t)*SST + o_l] = f2tf(e[t]);
    }
}

__device__ __forceinline__ void store_tile_B(uint32_t* Bs, const float4* pb,
                                             int k_l, int n4) {
    #pragma unroll
    for (int q = 0; q < 4; q++) {
        uint4 v = make_uint4(f2tf(pb[q].x), f2tf(pb[q].y), f2tf(pb[q].z), f2tf(pb[q].w));
        *(uint4*)&Bs[(k_l + q*8)*SST + n4] = v;
    }
}

__device__ __forceinline__ void compute_tile(const uint32_t* As, const uint32_t* Bs,
                                             float acc[4][4][4],
                                             int m0w, int n0w, int g, int tig) {
    #pragma unroll
    for (int kk = 0; kk < 4; kk++) {
        uint32_t af[4][4], bf[4][2];
        int kb = kk*8 + tig;
        #pragma unroll
        for (int mf = 0; mf < 4; mf++) {
            int m = m0w + mf*16 + g;
            af[mf][0] = As[kb*SST + m];
            af[mf][1] = As[kb*SST + m + 8];
            af[mf][2] = As[(kb+4)*SST + m];
            af[mf][3] = As[(kb+4)*SST + m + 8];
        }
        #pragma unroll
        for (int nf = 0; nf < 4; nf++) {
            int n = n0w + nf*8 + g;
            bf[nf][0] = Bs[kb*SST + n];
            bf[nf][1] = Bs[(kb+4)*SST + n];
        }
        #pragma unroll
        for (int mf = 0; mf < 4; mf++)
            #pragma unroll
            for (int nf = 0; nf < 4; nf++)
                mma_tf32(acc[mf][nf], af[mf], bf[nf]);
    }
}

// ---------------- K0: zero the stat accumulators ----------------
__global__ void zero_stats_kernel() {
    int t = threadIdx.x;
    g_sum1[t] = 0.f; g_sumsq1[t] = 0.f;
    g_sum2[t] = 0.f; g_sumsq2[t] = 0.f;
}

// ---------------- K1: 3-NN + inverse-distance weights ----------------
__global__ void knn_kernel(const float* __restrict__ unknown,
                           const float* __restrict__ known) {
    __shared__ float skx[MM], sky[MM], skz[MM], skn[MM];
    int b = blockIdx.y;
    const float* kb = known + (size_t)b * MM * 3;
    for (int m = threadIdx.x; m < MM; m += blockDim.x) {
        float x = kb[m*3+0], y = kb[m*3+1], z = kb[m*3+2];
        skx[m] = x; sky[m] = y; skz[m] = z; skn[m] = x*x + y*y + z*z;
    }
    __syncthreads();

    int n = blockIdx.x * blockDim.x + threadIdx.x;
    const float* u = unknown + ((size_t)b * NN + n) * 3;
    float ux = u[0], uy = u[1], uz = u[2];
    float un2 = ux*ux + uy*uy + uz*uz;

    float d0 = FLT_MAX, d1 = FLT_MAX, d2 = FLT_MAX;
    int   i0 = 0, i1 = 0, i2 = 0;
    #pragma unroll 4
    for (int m = 0; m < MM; m++) {
        float d = un2 + skn[m] - 2.0f * (ux*skx[m] + uy*sky[m] + uz*skz[m]);
        if (d < d0)      { d2 = d1; i2 = i1; d1 = d0; i1 = i0; d0 = d; i0 = m; }
        else if (d < d1) { d2 = d1; i2 = i1; d1 = d;  i1 = m; }
        else if (d < d2) { d2 = d;  i2 = m; }
    }
    d0 = fmaxf(d0, 0.f); d1 = fmaxf(d1, 0.f); d2 = fmaxf(d2, 0.f);
    float r0 = 1.0f / (sqrtf(d0) + 1e-8f);
    float r1 = 1.0f / (sqrtf(d1) + 1e-8f);
    float r2 = 1.0f / (sqrtf(d2) + 1e-8f);
    float inv = 1.0f / (r0 + r1 + r2);
    size_t base = ((size_t)b * NN + n) * 3;
    g_wgt[base+0] = r0 * inv; g_wgt[base+1] = r1 * inv; g_wgt[base+2] = r2 * inv;
    g_idx[base+0] = i0; g_idx[base+1] = i1; g_idx[base+2] = i2;
}

// ---------------- K2: Zt[m, o] = sum_k kf[k, m] * W1a[o, k]  per slice ----------------
// A-side (rows) = m positions, B-side (cols) = o channels; writes Zt directly.
__global__ __launch_bounds__(256, 2) void zgemm_kernel(
        const float* __restrict__ W1, const float* __restrict__ kf) {
    __shared__ uint32_t As[TILE_WORDS];
    __shared__ uint32_t Bs[TILE_WORDS];

    int slice = blockIdx.z; int b = slice >> 2, r = slice & 3;
    int m0t = blockIdx.x * TM, o0 = blockIdx.y * TN;
    int tid = threadIdx.x, lane = tid & 31, wid = tid >> 5;
    int g = lane >> 2, tig = lane & 3;
    int m0w = (wid & 1) * 64, n0w = (wid >> 1) * 32;

    float acc[4][4][4];
    #pragma unroll
    for (int i = 0; i < 4; i++)
        #pragma unroll
        for (int j = 0; j < 4; j++)
            #pragma unroll
            for (int e = 0; e < 4; e++) acc[i][j][e] = 0.f;

    // A loader (m-contiguous rows of kf), B loader (k-contiguous rows of W1)
    const int k_l = tid >> 5;          // 0..7
    const int n4  = (tid & 31) * 4;    // m-cols (float4)
    const int o_l = tid >> 1;          // 0..127
    const int kB  = (tid & 1) * 16;

    const float* Asrc = kf + ((size_t)b*CC*NR + r) * MM;   // + k*NR*MM + m

    float4 pa[4], pb[4];
    #pragma unroll
    for (int q = 0; q < 4; q++) {
        int k = k_l + q*8;
        pa[q] = *(const float4*)&Asrc[(size_t)k*(NR*MM) + m0t + n4];
    }
    #pragma unroll
    for (int j = 0; j < 4; j++)
        pb[j] = *(const float4*)&W1[(size_t)(o0 + o_l)*CIN + kB + j*4];

    for (int k0 = 0; k0 < CC; k0 += BK) {
        store_tile_B(As, pa, k_l, n4);      // A tile stored m-contiguous
        store_tile_A(Bs, pb, o_l, kB);      // B tile scatter-stored per o row
        __syncthreads();

        if (k0 + BK < CC) {
            #pragma unroll
            for (int q = 0; q < 4; q++) {
                int k = k0 + BK + k_l + q*8;
                pa[q] = *(const float4*)&Asrc[(size_t)k*(NR*MM) + m0t + n4];
            }
            #pragma unroll
            for (int j = 0; j < 4; j++)
                pb[j] = *(const float4*)&W1[(size_t)(o0 + o_l)*CIN + (k0 + BK) + kB + j*4];
        }

        compute_tile(As, Bs, acc, m0w, n0w, g, tig);
        __syncthreads();
    }

    // epilogue: rows = m positions, cols = o channels (contiguous)
    float* Zts = g_Zt + (size_t)slice * MM * CO;
    #pragma unroll
    for (int mf = 0; mf < 4; mf++) {
        int m = m0t + m0w + mf*16 + g;
        #pragma unroll
        for (int nf = 0; nf < 4; nf++) {
            float* c = acc[mf][nf];
            float* base = Zts + (size_t)m*CO + o0 + n0w + nf*8 + 2*tig;
            *(float2*)base = make_float2(c[0], c[1]);
            *(float2*)(base + (size_t)8*CO) = make_float2(c[2], c[3]);
        }
    }
}

// ---------------- K3: GEMM1' : y1 = W1b @ uf + gather-interp(Zt) ----------------
__global__ __launch_bounds__(256, 2) void gemm1_kernel(
        const float* __restrict__ W1, const float* __restrict__ unknow_feats) {
    extern __shared__ uint32_t dynsmem[];
    uint32_t* Abuf[2] = { dynsmem,                dynsmem + TILE_WORDS   };
    uint32_t* Bbuf[2] = { dynsmem + 2*TILE_WORDS, dynsmem + 3*TILE_WORDS };
    __shared__ float sw[TN*3];
    __shared__ int   si[TN*3];

    int slice = blockIdx.z; int b = slice >> 2, r = slice & 3;
    int o0 = blockIdx.y * TM, n0 = blockIdx.x * TN;
    int tid = threadIdx.x, lane = tid & 31, wid = tid >> 5;
    int g = lane >> 2, tig = lane & 3;
    int m0w = (wid & 1) * 64, n0w = (wid >> 1) * 32;

    // stage interpolation weights/indices for this CTA's 128 positions
    for (int i = tid; i < TN*3; i += 256) {
        size_t base = ((size_t)b*NN + n0) * 3 + i;
        sw[i] = g_wgt[base];
        si[i] = g_idx[base];
    }

    float acc[4][4][4];
    #pragma unroll
    for (int i = 0; i < 4; i++)
        #pragma unroll
        for (int j = 0; j < 4; j++)
            #pragma unroll
            for (int e = 0; e < 4; e++) acc[i][j][e] = 0.f;

    const int o_l = tid >> 1;
    const int kA  = (tid & 1) * 16;
    const int k_l = tid >> 5;
    const int n4  = (tid & 31) * 4;

    const float* Bsrc = unknow_feats + ((size_t)b*CC*NR + r) * NN;   // + k*NR*NN

    float4 pa[4], pb[4];
    #pragma unroll
    for (int j = 0; j < 4; j++)
        pa[j] = *(const float4*)&W1[(size_t)(o0 + o_l)*CIN + CC + kA + j*4];
    #pragma unroll
    for (int q = 0; q < 4; q++) {
        int k = k_l + q*8;
        pb[q] = *(const float4*)&Bsrc[(size_t)k*(NR*NN) + n0 + n4];
    }

    // prologue: commit tile 0
    store_tile_A(Abuf[0], pa, o_l, kA);
    store_tile_B(Bbuf[0], pb, k_l, n4);
    __syncthreads();

    int p = 0;
    for (int k0 = 0; k0 < CC; k0 += BK) {
        bool has_next = (k0 + BK < CC);
        if (has_next) {
            #pragma unroll
            for (int j = 0; j < 4; j++)
                pa[j] = *(const float4*)&W1[(size_t)(o0 + o_l)*CIN + CC + (k0 + BK) + kA + j*4];
            #pragma unroll
            for (int q = 0; q < 4; q++) {
                int k = k0 + BK + k_l + q*8;
                pb[q] = *(const float4*)&Bsrc[(size_t)k*(NR*NN) + n0 + n4];
            }
        }

        compute_tile(Abuf[p], Bbuf[p], acc, m0w, n0w, g, tig);

        if (has_next) {
            store_tile_A(Abuf[p^1], pa, o_l, kA);
            store_tile_B(Bbuf[p^1], pb, k_l, n4);
        }
        __syncthreads();
        p ^= 1;
    }

    // ---- gather-interp: acc += sum_j w_j * Zt[m_j][o] ----
    const float* Zts = g_Zt + (size_t)slice * MM * CO;
    #pragma unroll
    for (int nf = 0; nf < 4; nf++) {
        #pragma unroll
        for (int e = 0; e < 2; e++) {
            int pl = n0w + nf*8 + 2*tig + e;     // local position 0..127
            float w0 = sw[pl*3+0], w1 = sw[pl*3+1], w2 = sw[pl*3+2];
            const float* r0 = Zts + (size_t)si[pl*3+0]*CO + o0;
            const float* r1 = Zts + (size_t)si[pl*3+1]*CO + o0;
            const float* r2 = Zts + (size_t)si[pl*3+2]*CO + o0;
            #pragma unroll
            for (int mf = 0; mf < 4; mf++) {
                int o = m0w + mf*16 + g;
                acc[mf][nf][e]   += w0*r0[o]   + w1*r1[o]   + w2*r2[o];
                acc[mf][nf][2+e] += w0*r0[o+8] + w1*r1[o+8] + w2*r2[o+8];
            }
        }
    }

    // epilogue: store y1 + per-channel stats
    #pragma unroll
    for (int mf = 0; mf < 4; mf++) {
        int o = o0 + m0w + mf*16 + g;
        float sl = 0.f, ssl = 0.f, sh = 0.f, ssh = 0.f;
        #pragma unroll
        for (int nf = 0; nf < 4; nf++) {
            float* c = acc[mf][nf];
            float* base = g_y1 + (((size_t)b*CO + o)*NR + r)*NN + n0 + n0w + nf*8 + 2*tig;
            *(float2*)base = make_float2(c[0], c[1]);
            *(float2*)(base + (size_t)8*NR*NN) = make_float2(c[2], c[3]);
            sl += c[0] + c[1];  ssl += c[0]*c[0] + c[1]*c[1];
            sh += c[2] + c[3];  ssh += c[2]*c[2] + c[3]*c[3];
        }
        sl  += __shfl_xor_sync(0xffffffffu, sl, 1);  sl  += __shfl_xor_sync(0xffffffffu, sl, 2);
        ssl += __shfl_xor_sync(0xffffffffu, ssl, 1); ssl += __shfl_xor_sync(0xffffffffu, ssl, 2);
        sh  += __shfl_xor_sync(0xffffffffu, sh, 1);  sh  += __shfl_xor_sync(0xffffffffu, sh, 2);
        ssh += __shfl_xor_sync(0xffffffffu, ssh, 1); ssh += __shfl_xor_sync(0xffffffffu, ssh, 2);
        if (tig == 0) {
            atomicAdd(&g_sum1[o], sl);     atomicAdd(&g_sumsq1[o], ssl);
            atomicAdd(&g_sum1[o+8], sh);   atomicAdd(&g_sumsq1[o+8], ssh);
        }
    }
}

// ---------------- stats: derive scale/shift for BN ----------------
__global__ void stats_kernel(const float* __restrict__ gamma,
                             const float* __restrict__ beta, int layer) {
    int c = threadIdx.x;
    float sum   = layer ? g_sum2[c]   : g_sum1[c];
    float sumsq = layer ? g_sumsq2[c] : g_sumsq1[c];
    const float invP = 1.0f / (float)PTOT;
    float mean = sum * invP;
    float var  = sumsq * invP - mean * mean;
    float s = gamma[c] * rsqrtf(var + 1e-5f);
    float t = beta[c] - mean * s;
    if (layer) { g_s2[c] = s; g_t2[c] = t; }
    else       { g_s1[c] = s; g_t1[c] = t; }
}

// GEMM2: y2[o,p] = sum_k W2[o,k] * relu(s1[k]*y1[k,p] + t1[k]); accumulate stats2
__global__ __launch_bounds__(256, 2) void gemm2_kernel(const float* __restrict__ W2) {
    extern __shared__ uint32_t dynsmem[];
    uint32_t* Abuf[2] = { dynsmem,                dynsmem + TILE_WORDS   };
    uint32_t* Bbuf[2] = { dynsmem + 2*TILE_WORDS, dynsmem + 3*TILE_WORDS };

    int slice = blockIdx.z; int b = slice >> 2, r = slice & 3;
    int o0 = blockIdx.y * TM, n0 = blockIdx.x * TN;
    int tid = threadIdx.x, lane = tid & 31, wid = tid >> 5;
    int g = lane >> 2, tig = lane & 3;
    int m0w = (wid & 1) * 64, n0w = (wid >> 1) * 32;

    float acc[4][4][4];
    #pragma unroll
    for (int i = 0; i < 4; i++)
        #pragma unroll
        for (int j = 0; j < 4; j++)
            #pragma unroll
            for (int e = 0; e < 4; e++) acc[i][j][e] = 0.f;

    const int o_l = tid >> 1;
    const int kA  = (tid & 1) * 16;
    const int k_l = tid >> 5;
    const int n4  = (tid & 31) * 4;

    const float* Bsrc = g_y1 + ((size_t)b*CO*NR + r) * NN;

    float4 pa[4], pb[4];
    float  ps[4], pt[4];

    #pragma unroll
    for (int j = 0; j < 4; j++)
        pa[j] = *(const float4*)&W2[(size_t)(o0 + o_l)*CO + kA + j*4];
    #pragma unroll
    for (int q = 0; q < 4; q++) {
        int k = k_l + q*8;
        pb[q] = *(const float4*)&Bsrc[(size_t)k*(NR*NN) + n0 + n4];
        ps[q] = g_s1[k]; pt[q] = g_t1[k];
    }

    // prologue: BN+ReLU on B, commit tile 0
    store_tile_A(Abuf[0], pa, o_l, kA);
    {
        float4 pr[4];
        #pragma unroll
        for (int q = 0; q < 4; q++) {
            pr[q].x = fmaxf(fmaf(ps[q], pb[q].x, pt[q]), 0.f);
            pr[q].y = fmaxf(fmaf(ps[q], pb[q].y, pt[q]), 0.f);
            pr[q].z = fmaxf(fmaf(ps[q], pb[q].z, pt[q]), 0.f);
            pr[q].w = fmaxf(fmaf(ps[q], pb[q].w, pt[q]), 0.f);
        }
        store_tile_B(Bbuf[0], pr, k_l, n4);
    }
    __syncthreads();

    int p = 0;
    for (int k0 = 0; k0 < CO; k0 += BK) {
        bool has_next = (k0 + BK < CO);
        if (has_next) {
            #pragma unroll
            for (int j = 0; j < 4; j++)
                pa[j] = *(const float4*)&W2[(size_t)(o0 + o_l)*CO + (k0 + BK) + kA + j*4];
            #pragma unroll
            for (int q = 0; q < 4; q++) {
                int k = k0 + BK + k_l + q*8;
                pb[q] = *(const float4*)&Bsrc[(size_t)k*(NR*NN) + n0 + n4];
                ps[q] = g_s1[k]; pt[q] = g_t1[k];
            }
        }

        compute_tile(Abuf[p], Bbuf[p], acc, m0w, n0w, g, tig);

        if (has_next) {
            store_tile_A(Abuf[p^1], pa, o_l, kA);
            float4 pr[4];
            #pragma unroll
            for (int q = 0; q < 4; q++) {
                pr[q].x = fmaxf(fmaf(ps[q], pb[q].x, pt[q]), 0.f);
                pr[q].y = fmaxf(fmaf(ps[q], pb[q].y, pt[q]), 0.f);
                pr[q].z = fmaxf(fmaf(ps[q], pb[q].z, pt[q]), 0.f);
                pr[q].w = fmaxf(fmaf(ps[q], pb[q].w, pt[q]), 0.f);
            }
            store_tile_B(Bbuf[p^1], pr, k_l, n4);
        }
        __syncthreads();
        p ^= 1;
    }

    #pragma unroll
    for (int mf = 0; mf < 4; mf++) {
        int o = o0 + m0w + mf*16 + g;
        float sl = 0.f, ssl = 0.f, sh = 0.f, ssh = 0.f;
        #pragma unroll
        for (int nf = 0; nf < 4; nf++) {
            float* c = acc[mf][nf];
            float* base = g_y2 + (((size_t)b*CO + o)*NR + r)*NN + n0 + n0w + nf*8 + 2*tig;
            *(float2*)base = make_float2(c[0], c[1]);
            *(float2*)(base + (size_t)8*NR*NN) = make_float2(c[2], c[3]);
            sl += c[0] + c[1];  ssl += c[0]*c[0] + c[1]*c[1];
            sh += c[2] + c[3];  ssh += c[2]*c[2] + c[3]*c[3];
        }
        sl  += __shfl_xor_sync(0xffffffffu, sl, 1);  sl  += __shfl_xor_sync(0xffffffffu, sl, 2);
        ssl += __shfl_xor_sync(0xffffffffu, ssl, 1); ssl += __shfl_xor_sync(0xffffffffu, ssl, 2);
        sh  += __shfl_xor_sync(0xffffffffu, sh, 1);  sh  += __shfl_xor_sync(0xffffffffu, sh, 2);
        ssh += __shfl_xor_sync(0xffffffffu, ssh, 1); ssh += __shfl_xor_sync(0xffffffffu, ssh, 2);
        if (tig == 0) {
            atomicAdd(&g_sum2[o], sl);     atomicAdd(&g_sumsq2[o], ssl);
            atomicAdd(&g_sum2[o+8], sh);   atomicAdd(&g_sumsq2[o+8], ssh);
        }
    }
}

// ---------------- final: BN2 + ReLU -> d_out ----------------
__global__ void final_kernel(float* __restrict__ out) {
    size_t i = (size_t)blockIdx.x * blockDim.x + threadIdx.x;
    size_t idx = i * 4;
    int o = (int)((idx >> 13) & 255);   // layout ((b*CO+o)*NR+r)*NN+n
    float s = g_s2[o], t = g_t2[o];
    float4 v = *(const float4*)&g_y2[idx];
    v.x = fmaxf(fmaf(s, v.x, t), 0.f);
    v.y = fmaxf(fmaf(s, v.y, t), 0.f);
    v.z = fmaxf(fmaf(s, v.z, t), 0.f);
    v.w = fmaxf(fmaf(s, v.w, t), 0.f);
    ((float4*)out)[i] = v;
}

// ---------------- launch ----------------
extern "C" void kernel_launch(void* const* d_in, const int* in_sizes, int n_in,
                              void* d_out, int out_size) {
    const float* unknown      = (const float*)d_in[0];
    const float* known        = (const float*)d_in[1];
    const float* unknow_feats = (const float*)d_in[2];
    const float* known_feats  = (const float*)d_in[3];
    const float* W1 = (const float*)d_in[4];
    const float* g1 = (const float*)d_in[5];
    const float* b1 = (const float*)d_in[6];
    const float* W2 = (const float*)d_in[7];
    const float* g2 = (const float*)d_in[8];
    const float* b2 = (const float*)d_in[9];
    float* out = (float*)d_out;

    // idempotent attribute sets (no allocation, host-side only)
    cudaFuncSetAttribute(gemm1_kernel, cudaFuncAttributeMaxDynamicSharedMemorySize, SMEMB);
    cudaFuncSetAttribute(gemm2_kernel, cudaFuncAttributeMaxDynamicSharedMemorySize, SMEMB);

    zero_stats_kernel<<<1, 256>>>();
    knn_kernel<<<dim3(NN/256, BB), 256>>>(unknown, known);
    zgemm_kernel<<<dim3(MM/TM, CO/TN, BB*NR), 256>>>(W1, known_feats);
    gemm1_kernel<<<dim3(NN/TN, CO/TM, BB*NR), 256, SMEMB>>>(W1, unknow_feats);
    stats_kernel<<<1, 256>>>(g1, b1, 0);
    gemm2_kernel<<<dim3(NN/TN, CO/TM, BB*NR), 256, SMEMB>>>(W2);
    stats_kernel<<<1, 256>>>(g2, b2, 1);
    final_kernel<<<(int)(((size_t)BB*CO*NR*NN/4 + 255) / 256), 256>>>(out);
}